// round 16
// baseline (speedup 1.0000x reference)
#include <cuda_runtime.h>
#include <cstdint>

#define BB 8
#define CC 64
#define NN 4096
#define CI 8
#define NF 165               // 1 + 8 + 36 + 120 features (deg <= 3)
#define NSP 128              // n-splits for moment partials (32 n each)
#define MPS (NF * 9)         // 1485 moments, layout [i][f] (i-major planes)

// ---------------- scratch (no allocation allowed) ----------------
__device__ __align__(16) float g_qf[BB * NN * 8];        // q  [b][n][8]
__device__ __align__(16) float g_kf[BB * NN * 8];        // k/sqrt(8) [b][m][8]
__device__ __align__(16) float g_vf[BB * NN * 8];        // v  [b][n][8]
__device__ __align__(16) float g_Mp[BB * NSP * MPS];     // moment partials
__device__ __align__(16) float g_Mf[BB * MPS];           // final moments

// ---------------- f32x2 helpers ----------------
__device__ __forceinline__ unsigned long long ffma2(unsigned long long a, unsigned long long b,
                                                    unsigned long long c) {
    unsigned long long d;
    asm("fma.rn.f32x2 %0, %1, %2, %3;" : "=l"(d) : "l"(a), "l"(b), "l"(c));
    return d;
}
__device__ __forceinline__ void up2(unsigned long long p, float& lo, float& hi) {
    asm("mov.b64 {%0,%1}, %2;" : "=f"(lo), "=f"(hi) : "l"(p));
}

// weighted deg-3 feature generation (q side), compile-time range -> unrolled
template <int I0, int I1, int F0>
__device__ __forceinline__ void gen3(float* sPsiT, int nn, const float (&u)[8]) {
    int f = F0;
#pragma unroll
    for (int i = I0; i < I1; i++)
#pragma unroll
        for (int j = i; j < 8; j++) {
            float dij = u[i] * u[j];
#pragma unroll
            for (int l = j; l < 8; l++) {
                float w = (i == j && j == l) ? 0.16666667f
                          : ((i == j || j == l) ? 0.5f : 1.0f);
                sPsiT[f * 34 + nn] = w * dij * u[l];
                f++;
            }
        }
}

// accumulate one feature's 9 moments into TWO accumulator sets (3 LDS shared)
__device__ __forceinline__ void acc2m(float* aA, float* aB, const float* sM2, int f,
                                      float mA, float mB) {
    const float4* Mp = reinterpret_cast<const float4*>(&sM2[f * 12]);
    float4 a = Mp[0], b = Mp[1];
    float m8 = sM2[f * 12 + 8];
    aA[0] = fmaf(mA, a.x, aA[0]); aB[0] = fmaf(mB, a.x, aB[0]);
    aA[1] = fmaf(mA, a.y, aA[1]); aB[1] = fmaf(mB, a.y, aB[1]);
    aA[2] = fmaf(mA, a.z, aA[2]); aB[2] = fmaf(mB, a.z, aB[2]);
    aA[3] = fmaf(mA, a.w, aA[3]); aB[3] = fmaf(mB, a.w, aB[3]);
    aA[4] = fmaf(mA, b.x, aA[4]); aB[4] = fmaf(mB, b.x, aB[4]);
    aA[5] = fmaf(mA, b.y, aA[5]); aB[5] = fmaf(mB, b.y, aB[5]);
    aA[6] = fmaf(mA, b.z, aA[6]); aB[6] = fmaf(mB, b.z, aB[6]);
    aA[7] = fmaf(mA, b.w, aA[7]); aB[7] = fmaf(mB, b.w, aB[7]);
    aA[8] = fmaf(mA, m8, aA[8]);  aB[8] = fmaf(mB, m8, aB[8]);
}

// evaluate features in [FLO, FHI) for two m-rows; loops fully unrolled, range
// guards fold at compile time.
template <int FLO, int FHI>
__device__ __forceinline__ void acc_range(float* aA, float* aB, const float* sM2,
                                          const float (&uA)[8], const float (&uB)[8]) {
    int f = 0;
    if (0 >= FLO && 0 < FHI) acc2m(aA, aB, sM2, 0, 1.0f, 1.0f);
    f = 1;
#pragma unroll
    for (int i = 0; i < 8; i++) {
        if (f >= FLO && f < FHI) acc2m(aA, aB, sM2, f, uA[i], uB[i]);
        f++;
    }
#pragma unroll
    for (int i = 0; i < 8; i++)
#pragma unroll
        for (int j = i; j < 8; j++) {
            if (f >= FLO && f < FHI)
                acc2m(aA, aB, sM2, f, uA[i] * uA[j], uB[i] * uB[j]);
            f++;
        }
#pragma unroll
    for (int i = 0; i < 8; i++)
#pragma unroll
        for (int j = i; j < 8; j++)
#pragma unroll
            for (int l = j; l < 8; l++) {
                if (f >= FLO && f < FHI)
                    acc2m(aA, aB, sM2, f, uA[i] * uA[j] * uA[l], uB[i] * uB[j] * uB[l]);
                f++;
            }
}

// ---------------- kernel 1: q/k/v projections (f32 out) --------------------
__global__ void __launch_bounds__(128) proj_kernel(const float* __restrict__ x,
                                                   const float* __restrict__ Wq,
                                                   const float* __restrict__ Wk,
                                                   const float* __restrict__ Wv) {
    __shared__ float swq[CI * CC], swk[CI * CC], swv[CI * CC];
    int tid = threadIdx.x;
    for (int i = tid; i < CI * CC; i += 128) {
        swq[i] = Wq[i]; swk[i] = Wk[i]; swv[i] = Wv[i];
    }
    __syncthreads();

    int wid = tid >> 5, lane = tid & 31;
    int quarter = lane >> 3, nl = lane & 7;
    int slot = blockIdx.x * 32 + wid * 8 + nl;     // grid 1024 -> 32768 slots
    int b = slot >> 12, n = slot & (NN - 1);

    float q[CI], k[CI], v[CI];
#pragma unroll
    for (int i = 0; i < CI; i++) { q[i] = 0.f; k[i] = 0.f; v[i] = 0.f; }

    const float* xp = x + (size_t)b * CC * NN + n;
    int c0 = quarter * 16;
#pragma unroll
    for (int j = 0; j < 16; j++) {
        int c = c0 + j;
        float xv = xp[(size_t)c * NN];
#pragma unroll
        for (int i = 0; i < CI; i++) {
            q[i] = fmaf(swq[i * CC + c], xv, q[i]);
            k[i] = fmaf(swk[i * CC + c], xv, k[i]);
            v[i] = fmaf(swv[i * CC + c], xv, v[i]);
        }
    }
#pragma unroll
    for (int i = 0; i < CI; i++) {
        q[i] += __shfl_xor_sync(0xffffffffu, q[i], 8);
        k[i] += __shfl_xor_sync(0xffffffffu, k[i], 8);
        v[i] += __shfl_xor_sync(0xffffffffu, v[i], 8);
        q[i] += __shfl_xor_sync(0xffffffffu, q[i], 16);
        k[i] += __shfl_xor_sync(0xffffffffu, k[i], 16);
        v[i] += __shfl_xor_sync(0xffffffffu, v[i], 16);
    }
    if (quarter == 0) {
        const float KS = 0.35355339f;   // 1/sqrt(8) folded into k
        size_t base = ((size_t)b * NN + n) * 8;
        *reinterpret_cast<float4*>(&g_qf[base]) = make_float4(q[0], q[1], q[2], q[3]);
        *reinterpret_cast<float4*>(&g_qf[base + 4]) = make_float4(q[4], q[5], q[6], q[7]);
        *reinterpret_cast<float4*>(&g_kf[base]) =
            make_float4(k[0] * KS, k[1] * KS, k[2] * KS, k[3] * KS);
        *reinterpret_cast<float4*>(&g_kf[base + 4]) =
            make_float4(k[4] * KS, k[5] * KS, k[6] * KS, k[7] * KS);
        *reinterpret_cast<float4*>(&g_vf[base]) = make_float4(v[0], v[1], v[2], v[3]);
        *reinterpret_cast<float4*>(&g_vf[base + 4]) = make_float4(v[4], v[5], v[6], v[7]);
    }
}

// ---------------- kernel 2: moments M[i,f] = sum_n v_i(n) w_f psi_f(q_n) ---
__global__ void __launch_bounds__(192) moments_kernel() {
    __shared__ __align__(16) float sPsiT[NF * 34];   // 22.4 KB
    __shared__ __align__(16) float sv[16 * 20];      // v pairs, flat, padded

    int tid = threadIdx.x;
    int b = blockIdx.x >> 7, sp = blockIdx.x & 127;
    int nbase = sp * 32;
    int part = tid >> 5, nn = tid & 31;
    int n = nbase + nn;

    float u[8];
    {
        size_t base = ((size_t)b * NN + n) * 8;
        float4 a = *reinterpret_cast<const float4*>(&g_qf[base]);
        float4 c = *reinterpret_cast<const float4*>(&g_qf[base + 4]);
        u[0] = a.x; u[1] = a.y; u[2] = a.z; u[3] = a.w;
        u[4] = c.x; u[5] = c.y; u[6] = c.z; u[7] = c.w;
    }

    if (part == 0) {
        sPsiT[0 * 34 + nn] = 1.0f;
#pragma unroll
        for (int i = 0; i < 8; i++) sPsiT[(1 + i) * 34 + nn] = u[i];
        size_t vb = ((size_t)b * NN + n) * 8;
        float4 a = *reinterpret_cast<const float4*>(&g_vf[vb]);
        float4 c = *reinterpret_cast<const float4*>(&g_vf[vb + 4]);
        float vv[9] = {a.x, a.y, a.z, a.w, c.x, c.y, c.z, c.w, 1.0f};
        int np = nn >> 1, h = nn & 1;
#pragma unroll
        for (int i = 0; i < 9; i++) sv[np * 20 + i * 2 + h] = vv[i];
    } else if (part == 1) {
        int f = 9;
#pragma unroll
        for (int i = 0; i < 8; i++)
#pragma unroll
            for (int j = i; j < 8; j++) {
                float w = (i == j) ? 0.5f : 1.0f;
                sPsiT[f * 34 + nn] = w * u[i] * u[j];
                f++;
            }
    } else if (part == 2) {
        gen3<0, 1, 45>(sPsiT, nn, u);
    } else if (part == 3) {
        gen3<1, 2, 81>(sPsiT, nn, u);
    } else if (part == 4) {
        gen3<2, 4, 109>(sPsiT, nn, u);
    } else {
        gen3<4, 8, 145>(sPsiT, nn, u);
    }
    __syncthreads();

    if (tid < NF) {
        int f = tid;
        unsigned long long acc[9];
#pragma unroll
        for (int i = 0; i < 9; i++) acc[i] = 0ull;
#pragma unroll
        for (int np = 0; np < 16; np++) {
            unsigned long long pp =
                *reinterpret_cast<const unsigned long long*>(&sPsiT[f * 34 + 2 * np]);
            const float* vv = &sv[np * 20];
            ulonglong2 v01 = *reinterpret_cast<const ulonglong2*>(vv);
            ulonglong2 v23 = *reinterpret_cast<const ulonglong2*>(vv + 4);
            ulonglong2 v45 = *reinterpret_cast<const ulonglong2*>(vv + 8);
            ulonglong2 v67 = *reinterpret_cast<const ulonglong2*>(vv + 12);
            unsigned long long v8 = *reinterpret_cast<const unsigned long long*>(vv + 16);
            acc[0] = ffma2(pp, v01.x, acc[0]);
            acc[1] = ffma2(pp, v01.y, acc[1]);
            acc[2] = ffma2(pp, v23.x, acc[2]);
            acc[3] = ffma2(pp, v23.y, acc[3]);
            acc[4] = ffma2(pp, v45.x, acc[4]);
            acc[5] = ffma2(pp, v45.y, acc[5]);
            acc[6] = ffma2(pp, v67.x, acc[6]);
            acc[7] = ffma2(pp, v67.y, acc[7]);
            acc[8] = ffma2(pp, v8, acc[8]);
        }
        size_t ob = ((size_t)b * NSP + sp) * MPS;
#pragma unroll
        for (int i = 0; i < 9; i++) {
            float lo, hi;
            up2(acc[i], lo, hi);
            g_Mp[ob + (size_t)i * NF + f] = lo + hi;   // [i][f]: coalesced across f
        }
    }
}

// ---------------- kernel 2b: reduce partials (48 CTAs, MLP-deep) -----------
__global__ void __launch_bounds__(256) reduce_kernel() {
    int b = blockIdx.x / 6, chunk = blockIdx.x % 6;
    if (threadIdx.x >= 248) return;
    int out = chunk * 248 + threadIdx.x;
    if (out >= MPS) return;
    float s = 0.f;
#pragma unroll 32
    for (int sp = 0; sp < NSP; sp++)
        s += g_Mp[((size_t)b * NSP + sp) * MPS + out];
    g_Mf[(size_t)b * MPS + out] = s;
}

// ---------------- kernel 3: eval + normalize + Wout epilogue ---------------
// grid 512 (b = bx>>6, mt = bx&63; 64 m each), 256 threads:
// mm = tid&31 -> TWO m's (m0+mm, m0+mm+32); fq = tid>>5 -> 8 feature groups.
__global__ void __launch_bounds__(256) eval_kernel(const float* __restrict__ x,
                                                   const float* __restrict__ Wout,
                                                   float* __restrict__ out) {
    __shared__ __align__(16) float sM2[NF * 12];   // f-major [f][12] (9 used)
    __shared__ float sW[CC * CI];
    __shared__ float sPart[8][64][9];
    __shared__ float sAtt[64][9];

    int tid = threadIdx.x;
    int b = blockIdx.x >> 6, mt = blockIdx.x & 63;
    int m0 = mt * 64;

    for (int idx = tid; idx < MPS; idx += 256) {
        int i = idx / NF, f = idx - i * NF;        // source layout [i][f]
        sM2[f * 12 + i] = g_Mf[(size_t)b * MPS + idx];
    }
    for (int i = tid; i < CC * CI; i += 256) sW[i] = Wout[i];
    __syncthreads();

    int mm = tid & 31, fq = tid >> 5;
    int mA = m0 + mm, mB = m0 + mm + 32;

    float uA[8], uB[8];
    {
        size_t ba = ((size_t)b * NN + mA) * 8;
        size_t bb2 = ((size_t)b * NN + mB) * 8;
        float4 a0 = *reinterpret_cast<const float4*>(&g_kf[ba]);
        float4 a1 = *reinterpret_cast<const float4*>(&g_kf[ba + 4]);
        float4 b0 = *reinterpret_cast<const float4*>(&g_kf[bb2]);
        float4 b1 = *reinterpret_cast<const float4*>(&g_kf[bb2 + 4]);
        uA[0] = a0.x; uA[1] = a0.y; uA[2] = a0.z; uA[3] = a0.w;
        uA[4] = a1.x; uA[5] = a1.y; uA[6] = a1.z; uA[7] = a1.w;
        uB[0] = b0.x; uB[1] = b0.y; uB[2] = b0.z; uB[3] = b0.w;
        uB[4] = b1.x; uB[5] = b1.y; uB[6] = b1.z; uB[7] = b1.w;
    }

    float aA[9], aB[9];
#pragma unroll
    for (int i = 0; i < 9; i++) { aA[i] = 0.f; aB[i] = 0.f; }

    // 8 balanced feature groups: {0,21,42,63,84,105,126,146,165}
    if (fq == 0)      acc_range<0, 21>(aA, aB, sM2, uA, uB);
    else if (fq == 1) acc_range<21, 42>(aA, aB, sM2, uA, uB);
    else if (fq == 2) acc_range<42, 63>(aA, aB, sM2, uA, uB);
    else if (fq == 3) acc_range<63, 84>(aA, aB, sM2, uA, uB);
    else if (fq == 4) acc_range<84, 105>(aA, aB, sM2, uA, uB);
    else if (fq == 5) acc_range<105, 126>(aA, aB, sM2, uA, uB);
    else if (fq == 6) acc_range<126, 146>(aA, aB, sM2, uA, uB);
    else              acc_range<146, 165>(aA, aB, sM2, uA, uB);

#pragma unroll
    for (int t = 0; t < 9; t++) {
        sPart[fq][mm][t] = aA[t];
        sPart[fq][mm + 32][t] = aB[t];
    }
    __syncthreads();

    // parallel combine: 576 outputs over 256 threads
    for (int idx = tid; idx < 576; idx += 256) {
        int ml = idx / 9, t = idx - ml * 9;
        float s = 0.f;
#pragma unroll
        for (int p = 0; p < 8; p++) s += sPart[p][ml][t];
        sAtt[ml][t] = s;
    }
    __syncthreads();

    // epilogue: out = x + 0.1 * Wout @ att ; thread (ml, cq): 16 channels
    int ml = tid & 63, cq = tid >> 6;
    float inv = 1.0f / sAtt[ml][8];
    float att[8];
#pragma unroll
    for (int i = 0; i < 8; i++) att[i] = sAtt[ml][i] * inv;

    int mg = m0 + ml;
    const float* xp = x + (size_t)b * CC * NN + mg;
    float* op = out + (size_t)b * CC * NN + mg;
#pragma unroll
    for (int j = 0; j < 16; j++) {
        int c = cq * 16 + j;
        float o = 0.f;
#pragma unroll
        for (int i = 0; i < 8; i++) o = fmaf(sW[c * CI + i], att[i], o);
        op[(size_t)c * NN] = fmaf(0.1f, o, xp[(size_t)c * NN]);
    }
}

// ---------------- launch ----------------
extern "C" void kernel_launch(void* const* d_in, const int* in_sizes, int n_in,
                              void* d_out, int out_size) {
    const float* x = (const float*)d_in[0];
    const float* Wq = (const float*)d_in[1];
    const float* Wk = (const float*)d_in[2];
    const float* Wv = (const float*)d_in[3];
    const float* Wout = (const float*)d_in[4];
    float* out = (float*)d_out;

    proj_kernel<<<1024, 128>>>(x, Wq, Wk, Wv);
    moments_kernel<<<1024, 192>>>();
    reduce_kernel<<<48, 256>>>();
    eval_kernel<<<512, 256>>>(x, Wout, out);
}

// round 17
// speedup vs baseline: 1.0828x; 1.0828x over previous
#include <cuda_runtime.h>
#include <cstdint>

#define BB 8
#define CC 64
#define NN 4096
#define CI 8
#define NF 165               // 1 + 8 + 36 + 120 features (deg <= 3)
#define NSP 128              // n-splits for moment partials (32 n each)
#define MPS (NF * 9)         // 1485 moments, layout [i][f] (i-major planes)

// ---------------- scratch (no allocation allowed) ----------------
__device__ __align__(16) float g_qf[BB * NN * 8];        // q  [b][n][8]
__device__ __align__(16) float g_kf[BB * NN * 8];        // k/sqrt(8) [b][m][8]
__device__ __align__(16) float g_vf[BB * NN * 8];        // v  [b][n][8]
__device__ __align__(16) float g_Mp[BB * NSP * MPS];     // moment partials
__device__ __align__(16) float g_Mf[BB * MPS];           // final moments

// ---------------- f32x2 helpers ----------------
__device__ __forceinline__ unsigned long long ffma2(unsigned long long a, unsigned long long b,
                                                    unsigned long long c) {
    unsigned long long d;
    asm("fma.rn.f32x2 %0, %1, %2, %3;" : "=l"(d) : "l"(a), "l"(b), "l"(c));
    return d;
}
__device__ __forceinline__ void up2(unsigned long long p, float& lo, float& hi) {
    asm("mov.b64 {%0,%1}, %2;" : "=f"(lo), "=f"(hi) : "l"(p));
}

// weighted deg-3 feature generation (q side), compile-time range -> unrolled
template <int I0, int I1, int F0>
__device__ __forceinline__ void gen3(float* sPsiT, int nn, const float (&u)[8]) {
    int f = F0;
#pragma unroll
    for (int i = I0; i < I1; i++)
#pragma unroll
        for (int j = i; j < 8; j++) {
            float dij = u[i] * u[j];
#pragma unroll
            for (int l = j; l < 8; l++) {
                float w = (i == j && j == l) ? 0.16666667f
                          : ((i == j || j == l) ? 0.5f : 1.0f);
                sPsiT[f * 34 + nn] = w * dij * u[l];
                f++;
            }
        }
}

// accumulate one feature's 9 moments (k side): 3 LDS from f-major sM2[f][12]
__device__ __forceinline__ void acc1(float* acc, const float* sM2, int f, float mon) {
    const float4* Mp = reinterpret_cast<const float4*>(&sM2[f * 12]);
    float4 a = Mp[0], b = Mp[1];
    float m8 = sM2[f * 12 + 8];
    acc[0] = fmaf(mon, a.x, acc[0]);
    acc[1] = fmaf(mon, a.y, acc[1]);
    acc[2] = fmaf(mon, a.z, acc[2]);
    acc[3] = fmaf(mon, a.w, acc[3]);
    acc[4] = fmaf(mon, b.x, acc[4]);
    acc[5] = fmaf(mon, b.y, acc[5]);
    acc[6] = fmaf(mon, b.z, acc[6]);
    acc[7] = fmaf(mon, b.w, acc[7]);
    acc[8] = fmaf(mon, m8, acc[8]);
}
template <int I0, int I1, int F0>
__device__ __forceinline__ void acc3(float* acc, const float* sM2, const float (&u)[8]) {
    int f = F0;
#pragma unroll
    for (int i = I0; i < I1; i++)
#pragma unroll
        for (int j = i; j < 8; j++) {
            float dij = u[i] * u[j];
#pragma unroll
            for (int l = j; l < 8; l++) {
                acc1(acc, sM2, f, dij * u[l]);
                f++;
            }
        }
}

// ---------------- kernel 1: q/k/v projections (transposed-weight smem) -----
__global__ void __launch_bounds__(128) proj_kernel(const float* __restrict__ x,
                                                   const float* __restrict__ Wq,
                                                   const float* __restrict__ Wk,
                                                   const float* __restrict__ Wv) {
    __shared__ __align__(16) float swqT[CC * 8], swkT[CC * 8], swvT[CC * 8];
    int tid = threadIdx.x;
    for (int idx = tid; idx < CI * CC; idx += 128) {
        int i = idx / CC, c = idx - i * CC;        // source [i][c] -> dest [c][i]
        swqT[c * 8 + i] = Wq[idx];
        swkT[c * 8 + i] = Wk[idx];
        swvT[c * 8 + i] = Wv[idx];
    }
    __syncthreads();

    int wid = tid >> 5, lane = tid & 31;
    int quarter = lane >> 3, nl = lane & 7;
    int slot = blockIdx.x * 32 + wid * 8 + nl;     // grid 1024 -> 32768 slots
    int b = slot >> 12, n = slot & (NN - 1);

    float q[CI], k[CI], v[CI];
#pragma unroll
    for (int i = 0; i < CI; i++) { q[i] = 0.f; k[i] = 0.f; v[i] = 0.f; }

    const float* xp = x + (size_t)b * CC * NN + n;
    int c0 = quarter * 16;
#pragma unroll
    for (int j = 0; j < 16; j++) {
        int c = c0 + j;
        float xv = xp[(size_t)c * NN];
        const float4* wq = reinterpret_cast<const float4*>(&swqT[c * 8]);
        const float4* wk = reinterpret_cast<const float4*>(&swkT[c * 8]);
        const float4* wv = reinterpret_cast<const float4*>(&swvT[c * 8]);
        float4 q0 = wq[0], q1 = wq[1];
        float4 k0 = wk[0], k1 = wk[1];
        float4 v0 = wv[0], v1 = wv[1];
        q[0] = fmaf(q0.x, xv, q[0]); q[1] = fmaf(q0.y, xv, q[1]);
        q[2] = fmaf(q0.z, xv, q[2]); q[3] = fmaf(q0.w, xv, q[3]);
        q[4] = fmaf(q1.x, xv, q[4]); q[5] = fmaf(q1.y, xv, q[5]);
        q[6] = fmaf(q1.z, xv, q[6]); q[7] = fmaf(q1.w, xv, q[7]);
        k[0] = fmaf(k0.x, xv, k[0]); k[1] = fmaf(k0.y, xv, k[1]);
        k[2] = fmaf(k0.z, xv, k[2]); k[3] = fmaf(k0.w, xv, k[3]);
        k[4] = fmaf(k1.x, xv, k[4]); k[5] = fmaf(k1.y, xv, k[5]);
        k[6] = fmaf(k1.z, xv, k[6]); k[7] = fmaf(k1.w, xv, k[7]);
        v[0] = fmaf(v0.x, xv, v[0]); v[1] = fmaf(v0.y, xv, v[1]);
        v[2] = fmaf(v0.z, xv, v[2]); v[3] = fmaf(v0.w, xv, v[3]);
        v[4] = fmaf(v1.x, xv, v[4]); v[5] = fmaf(v1.y, xv, v[5]);
        v[6] = fmaf(v1.z, xv, v[6]); v[7] = fmaf(v1.w, xv, v[7]);
    }
#pragma unroll
    for (int i = 0; i < CI; i++) {
        q[i] += __shfl_xor_sync(0xffffffffu, q[i], 8);
        k[i] += __shfl_xor_sync(0xffffffffu, k[i], 8);
        v[i] += __shfl_xor_sync(0xffffffffu, v[i], 8);
        q[i] += __shfl_xor_sync(0xffffffffu, q[i], 16);
        k[i] += __shfl_xor_sync(0xffffffffu, k[i], 16);
        v[i] += __shfl_xor_sync(0xffffffffu, v[i], 16);
    }
    if (quarter == 0) {
        const float KS = 0.35355339f;   // 1/sqrt(8) folded into k
        size_t base = ((size_t)b * NN + n) * 8;
        *reinterpret_cast<float4*>(&g_qf[base]) = make_float4(q[0], q[1], q[2], q[3]);
        *reinterpret_cast<float4*>(&g_qf[base + 4]) = make_float4(q[4], q[5], q[6], q[7]);
        *reinterpret_cast<float4*>(&g_kf[base]) =
            make_float4(k[0] * KS, k[1] * KS, k[2] * KS, k[3] * KS);
        *reinterpret_cast<float4*>(&g_kf[base + 4]) =
            make_float4(k[4] * KS, k[5] * KS, k[6] * KS, k[7] * KS);
        *reinterpret_cast<float4*>(&g_vf[base]) = make_float4(v[0], v[1], v[2], v[3]);
        *reinterpret_cast<float4*>(&g_vf[base + 4]) = make_float4(v[4], v[5], v[6], v[7]);
    }
}

// ---------------- kernel 2: moments M[i,f] = sum_n v_i(n) w_f psi_f(q_n) ---
__global__ void __launch_bounds__(192) moments_kernel() {
    __shared__ __align__(16) float sPsiT[NF * 34];   // 22.4 KB
    __shared__ __align__(16) float sv[16 * 20];      // v pairs, flat, padded

    int tid = threadIdx.x;
    int b = blockIdx.x >> 7, sp = blockIdx.x & 127;
    int nbase = sp * 32;
    int part = tid >> 5, nn = tid & 31;
    int n = nbase + nn;

    float u[8];
    {
        size_t base = ((size_t)b * NN + n) * 8;
        float4 a = *reinterpret_cast<const float4*>(&g_qf[base]);
        float4 c = *reinterpret_cast<const float4*>(&g_qf[base + 4]);
        u[0] = a.x; u[1] = a.y; u[2] = a.z; u[3] = a.w;
        u[4] = c.x; u[5] = c.y; u[6] = c.z; u[7] = c.w;
    }

    if (part == 0) {
        sPsiT[0 * 34 + nn] = 1.0f;
#pragma unroll
        for (int i = 0; i < 8; i++) sPsiT[(1 + i) * 34 + nn] = u[i];
        size_t vb = ((size_t)b * NN + n) * 8;
        float4 a = *reinterpret_cast<const float4*>(&g_vf[vb]);
        float4 c = *reinterpret_cast<const float4*>(&g_vf[vb + 4]);
        float vv[9] = {a.x, a.y, a.z, a.w, c.x, c.y, c.z, c.w, 1.0f};
        int np = nn >> 1, h = nn & 1;
#pragma unroll
        for (int i = 0; i < 9; i++) sv[np * 20 + i * 2 + h] = vv[i];
    } else if (part == 1) {
        int f = 9;
#pragma unroll
        for (int i = 0; i < 8; i++)
#pragma unroll
            for (int j = i; j < 8; j++) {
                float w = (i == j) ? 0.5f : 1.0f;
                sPsiT[f * 34 + nn] = w * u[i] * u[j];
                f++;
            }
    } else if (part == 2) {
        gen3<0, 1, 45>(sPsiT, nn, u);
    } else if (part == 3) {
        gen3<1, 2, 81>(sPsiT, nn, u);
    } else if (part == 4) {
        gen3<2, 4, 109>(sPsiT, nn, u);
    } else {
        gen3<4, 8, 145>(sPsiT, nn, u);
    }
    __syncthreads();

    if (tid < NF) {
        int f = tid;
        unsigned long long acc[9];
#pragma unroll
        for (int i = 0; i < 9; i++) acc[i] = 0ull;
#pragma unroll
        for (int np = 0; np < 16; np++) {
            unsigned long long pp =
                *reinterpret_cast<const unsigned long long*>(&sPsiT[f * 34 + 2 * np]);
            const float* vv = &sv[np * 20];
            ulonglong2 v01 = *reinterpret_cast<const ulonglong2*>(vv);
            ulonglong2 v23 = *reinterpret_cast<const ulonglong2*>(vv + 4);
            ulonglong2 v45 = *reinterpret_cast<const ulonglong2*>(vv + 8);
            ulonglong2 v67 = *reinterpret_cast<const ulonglong2*>(vv + 12);
            unsigned long long v8 = *reinterpret_cast<const unsigned long long*>(vv + 16);
            acc[0] = ffma2(pp, v01.x, acc[0]);
            acc[1] = ffma2(pp, v01.y, acc[1]);
            acc[2] = ffma2(pp, v23.x, acc[2]);
            acc[3] = ffma2(pp, v23.y, acc[3]);
            acc[4] = ffma2(pp, v45.x, acc[4]);
            acc[5] = ffma2(pp, v45.y, acc[5]);
            acc[6] = ffma2(pp, v67.x, acc[6]);
            acc[7] = ffma2(pp, v67.y, acc[7]);
            acc[8] = ffma2(pp, v8, acc[8]);
        }
        size_t ob = ((size_t)b * NSP + sp) * MPS;
#pragma unroll
        for (int i = 0; i < 9; i++) {
            float lo, hi;
            up2(acc[i], lo, hi);
            g_Mp[ob + (size_t)i * NF + f] = lo + hi;   // [i][f]: coalesced across f
        }
    }
}

// ---------------- kernel 2b: reduce partials (376 CTAs, shfl tree) ---------
// grid 376: b = bx/47, chunk = bx%47 (32 outputs each). 256 threads:
// out = chunk*32 + (tid>>3); spt = tid&7 sums 16 splits; shfl-reduce over spt.
__global__ void __launch_bounds__(256) reduce_kernel() {
    int b = blockIdx.x / 47, chunk = blockIdx.x % 47;
    int tid = threadIdx.x;
    int out = chunk * 32 + (tid >> 3);
    int spt = tid & 7;
    if (out >= MPS) return;
    float s = 0.f;
#pragma unroll
    for (int t = 0; t < 16; t++)
        s += g_Mp[((size_t)b * NSP + spt + t * 8) * MPS + out];
    s += __shfl_xor_sync(0xffffffffu, s, 1);
    s += __shfl_xor_sync(0xffffffffu, s, 2);
    s += __shfl_xor_sync(0xffffffffu, s, 4);
    if (spt == 0) g_Mf[(size_t)b * MPS + out] = s;
}

// ---------------- kernel 3: eval + normalize + Wout epilogue (R15 exact) ---
// grid 512 (b = bx>>6, mt = bx&63; 64 m each), 256 threads:
// mm = tid&63 (one m per thread), fq = tid>>6 (4-way feature split).
__global__ void __launch_bounds__(256) eval_kernel(const float* __restrict__ x,
                                                   const float* __restrict__ Wout,
                                                   float* __restrict__ out) {
    __shared__ __align__(16) float sM2[NF * 12];   // f-major [f][12] (9 used)
    __shared__ float sW[CC * CI];
    __shared__ float sPart[3 * 64 * 9];
    __shared__ float sAtt[64 * 9];

    int tid = threadIdx.x;
    int b = blockIdx.x >> 6, mt = blockIdx.x & 63;
    int m0 = mt * 64;

    for (int idx = tid; idx < MPS; idx += 256) {
        int i = idx / NF, f = idx - i * NF;        // source layout [i][f]
        sM2[f * 12 + i] = g_Mf[(size_t)b * MPS + idx];
    }
    for (int i = tid; i < CC * CI; i += 256) sW[i] = Wout[i];
    __syncthreads();

    int mm = tid & 63, fq = tid >> 6;
    int m = m0 + mm;

    float u[8];
    {
        size_t base = ((size_t)b * NN + m) * 8;
        float4 a = *reinterpret_cast<const float4*>(&g_kf[base]);
        float4 c = *reinterpret_cast<const float4*>(&g_kf[base + 4]);
        u[0] = a.x; u[1] = a.y; u[2] = a.z; u[3] = a.w;
        u[4] = c.x; u[5] = c.y; u[6] = c.z; u[7] = c.w;
    }

    float acc[9];
#pragma unroll
    for (int i = 0; i < 9; i++) acc[i] = 0.f;

    if (fq == 0) {
        acc1(acc, sM2, 0, 1.0f);                   // const
#pragma unroll
        for (int i = 0; i < 8; i++) acc1(acc, sM2, 1 + i, u[i]);   // linear
        int f = 9;                                 // deg-2
#pragma unroll
        for (int i = 0; i < 8; i++)
#pragma unroll
            for (int j = i; j < 8; j++) {
                acc1(acc, sM2, f, u[i] * u[j]);
                f++;
            }
    } else if (fq == 1) {
        acc3<0, 1, 45>(acc, sM2, u);
    } else if (fq == 2) {
        acc3<1, 3, 81>(acc, sM2, u);
    } else {
        acc3<3, 8, 130>(acc, sM2, u);
    }

    if (fq > 0) {
#pragma unroll
        for (int t = 0; t < 9; t++) sPart[((fq - 1) * 64 + mm) * 9 + t] = acc[t];
    }
    __syncthreads();
    if (fq == 0) {
#pragma unroll
        for (int p = 0; p < 3; p++)
#pragma unroll
            for (int t = 0; t < 9; t++) acc[t] += sPart[(p * 64 + mm) * 9 + t];
        float inv = 1.0f / acc[8];
#pragma unroll
        for (int i = 0; i < 8; i++) sAtt[mm * 9 + i] = acc[i] * inv;
    }
    __syncthreads();

    // epilogue: out = x + 0.1 * Wout @ att ; thread (ml, cq): 16 channels
    int ml = tid & 63, cq = tid >> 6;
    float att[8];
#pragma unroll
    for (int i = 0; i < 8; i++) att[i] = sAtt[ml * 9 + i];

    int mg = m0 + ml;
    const float* xp = x + (size_t)b * CC * NN + mg;
    float* op = out + (size_t)b * CC * NN + mg;
#pragma unroll
    for (int j = 0; j < 16; j++) {
        int c = cq * 16 + j;
        float o = 0.f;
#pragma unroll
        for (int i = 0; i < 8; i++) o = fmaf(sW[c * CI + i], att[i], o);
        op[(size_t)c * NN] = fmaf(0.1f, o, xp[(size_t)c * NN]);
    }
}

// ---------------- launch ----------------
extern "C" void kernel_launch(void* const* d_in, const int* in_sizes, int n_in,
                              void* d_out, int out_size) {
    const float* x = (const float*)d_in[0];
    const float* Wq = (const float*)d_in[1];
    const float* Wk = (const float*)d_in[2];
    const float* Wv = (const float*)d_in[3];
    const float* Wout = (const float*)d_in[4];
    float* out = (float*)d_out;

    proj_kernel<<<1024, 128>>>(x, Wq, Wk, Wv);
    moments_kernel<<<1024, 192>>>();
    reduce_kernel<<<376, 256>>>();
    eval_kernel<<<512, 256>>>(x, Wout, out);
}